// round 5
// baseline (speedup 1.0000x reference)
#include <cuda_runtime.h>
#include <math.h>

#define NN 100000
#define NE 1600000
#define HD 32

// ---- scratch (__device__ globals: no allocations allowed) ----
__device__ float g_emb_pre[NN * HD];   // pre-batchnorm node embedding
__device__ float g_emb[NN * HD];       // post-batchnorm node embedding
__device__ float g_q[NN * HD];         // emb @ W_bot           (per-src term)
__device__ float g_pb[NN * HD];        // emb @ (W_top-W_bot)+b (per-dst term)
__device__ float g_agg[NN * HD];       // final aggregated message (0 if empty)
__device__ float g_stats[4 * HD];      // sum1, sq1, sum2, sq2
__device__ int   g_deg[NN];            // in-degree histogram
__device__ int   g_off[NN + 1];        // CSR offsets
__device__ int   g_cur[NN];            // scatter cursors
__device__ int   g_srcs[NE];           // src node ids grouped by dst

__device__ __forceinline__ float eluf(float x) { return x > 0.f ? x : expm1f(x); }

// ---- K0: zero stats + degree histogram ----
__global__ void __launch_bounds__(1024) k_init() {
    int i = blockIdx.x * 1024 + threadIdx.x;
    if (i < 4 * HD) g_stats[i] = 0.f;
    if (i < NN) g_deg[i] = 0;
}

// ---- K1: node feature encoder -> g_emb_pre ----
__global__ void __launch_bounds__(256) k_embed(
    const float* __restrict__ x_cont, const int* __restrict__ x_cat,
    const float* __restrict__ W_cont, const float* __restrict__ b_cont,
    const float* __restrict__ T_chrg, const float* __restrict__ T_pdg,
    const float* __restrict__ T_pv,
    const float* __restrict__ W_cat,  const float* __restrict__ b_cat,
    const float* __restrict__ W_enc,  const float* __restrict__ b_enc)
{
    __shared__ float sWc[96], sbc[16], sTc[24], sTp[56], sTv[64];
    __shared__ float sWk[384], sbk[16], sWe[1024], sbe[32];
    int tid = threadIdx.x;
    for (int i = tid; i < 96;   i += 256) sWc[i] = W_cont[i];
    for (int i = tid; i < 16;   i += 256) sbc[i] = b_cont[i];
    for (int i = tid; i < 24;   i += 256) sTc[i] = T_chrg[i];
    for (int i = tid; i < 56;   i += 256) sTp[i] = T_pdg[i];
    for (int i = tid; i < 64;   i += 256) sTv[i] = T_pv[i];
    for (int i = tid; i < 384;  i += 256) sWk[i] = W_cat[i];
    for (int i = tid; i < 16;   i += 256) sbk[i] = b_cat[i];
    for (int i = tid; i < 1024; i += 256) sWe[i] = W_enc[i];
    for (int i = tid; i < 32;   i += 256) sbe[i] = b_enc[i];
    __syncthreads();

    int n = blockIdx.x * 256 + tid;
    if (n >= NN) return;

    float c[6];
    #pragma unroll
    for (int k = 0; k < 6; k++) c[k] = x_cont[n * 6 + k];
    float h1[16];
    #pragma unroll
    for (int j = 0; j < 16; j++) {
        float a = sbc[j];
        #pragma unroll
        for (int k = 0; k < 6; k++) a += c[k] * sWc[k * 16 + j];
        h1[j] = eluf(a);
    }

    int pdg_s = x_cat[n * 3 + 0];
    int chrg  = x_cat[n * 3 + 1];
    int pv    = x_cat[n * 3 + 2];
    int ap = pdg_s < 0 ? -pdg_s : pdg_s;
    int pi;
    switch (ap) {
        case 1:   pi = 0; break;
        case 2:   pi = 1; break;
        case 11:  pi = 2; break;
        case 13:  pi = 3; break;
        case 22:  pi = 4; break;
        case 130: pi = 5; break;
        default:  pi = 6; break;  // 211
    }
    float cat24[24];
    #pragma unroll
    for (int j = 0; j < 8; j++) {
        cat24[j]      = sTc[(chrg + 1) * 8 + j];
        cat24[8 + j]  = sTp[pi * 8 + j];
        cat24[16 + j] = sTv[pv * 8 + j];
    }
    float h2[16];
    #pragma unroll
    for (int j = 0; j < 16; j++) {
        float a = sbk[j];
        #pragma unroll
        for (int k = 0; k < 24; k++) a += cat24[k] * sWk[k * 16 + j];
        h2[j] = eluf(a);
    }

    float4* dst = (float4*)(g_emb_pre + (size_t)n * HD);
    #pragma unroll
    for (int jv = 0; jv < 8; jv++) {
        float o[4];
        #pragma unroll
        for (int u = 0; u < 4; u++) {
            int j = jv * 4 + u;
            float a = sbe[j];
            #pragma unroll
            for (int k = 0; k < 16; k++) a += h2[k] * sWe[k * 32 + j];
            #pragma unroll
            for (int k = 0; k < 16; k++) a += h1[k] * sWe[(16 + k) * 32 + j];
            o[u] = eluf(a);
        }
        dst[jv] = make_float4(o[0], o[1], o[2], o[3]);
    }
}

// ---- K2: degree histogram over destinations ----
__global__ void __launch_bounds__(256) k_hist(const int* __restrict__ ei) {
    int e = blockIdx.x * 256 + threadIdx.x;
    if (e < NE) atomicAdd(&g_deg[__ldg(&ei[NE + e])], 1);
}

// ---- K3: single-block exclusive scan -> g_off, g_cur ----
__global__ void __launch_bounds__(1024) k_scan() {
    __shared__ int part[1024];
    const int CH = (NN + 1023) / 1024;   // 98
    int t = threadIdx.x;
    int beg = t * CH;
    int end = beg + CH; if (end > NN) end = NN;
    int s = 0;
    for (int i = beg; i < end; i++) s += g_deg[i];
    part[t] = s;
    __syncthreads();
    for (int off = 1; off < 1024; off <<= 1) {
        int v = (t >= off) ? part[t - off] : 0;
        __syncthreads();
        part[t] += v;
        __syncthreads();
    }
    int run = (t == 0) ? 0 : part[t - 1];
    for (int i = beg; i < end; i++) {
        int d = g_deg[i];
        g_off[i] = run;
        g_cur[i] = run;
        run += d;
    }
    if (t == 1023) g_off[NN] = run;
}

// ---- K4: scatter src ids grouped by dst ----
__global__ void __launch_bounds__(256) k_scatter(const int* __restrict__ ei) {
    int e = blockIdx.x * 256 + threadIdx.x;
    if (e >= NE) return;
    int src = __ldg(&ei[e]);
    int dst = __ldg(&ei[NE + e]);
    int p = atomicAdd(&g_cur[dst], 1);
    g_srcs[p] = src;
}

// ---- K5a: column stats of g_emb_pre -> sum1/sq1 ----
__global__ void __launch_bounds__(256) k_stats_pre() {
    float acc_s = 0.f, acc_q = 0.f;
    long stride = (long)gridDim.x * 256;
    for (long i = (long)blockIdx.x * 256 + threadIdx.x; i < (long)NN * HD; i += stride) {
        float v = g_emb_pre[i];
        acc_s += v;
        acc_q += v * v;
    }
    __shared__ float ss[256], sq[256];
    int t = threadIdx.x;
    ss[t] = acc_s; sq[t] = acc_q;
    __syncthreads();
    if (t < 32) {
        #pragma unroll
        for (int w = 1; w < 8; w++) { acc_s += ss[t + 32 * w]; acc_q += sq[t + 32 * w]; }
        atomicAdd(&g_stats[t], acc_s);
        atomicAdd(&g_stats[HD + t], acc_q);
    }
}

// ---- K6: apply BN1 (params computed inline), q = emb@W_bot,
//          pb = emb@(W_top-W_bot)+b_msg ----
__global__ void __launch_bounds__(256) k_pq(const float* __restrict__ W_msg,
                                            const float* __restrict__ b_msg,
                                            const float* __restrict__ gamma,
                                            const float* __restrict__ beta) {
    __shared__ float sA[1024], sB[1024], sbm[32], ss1[32], st1[32];
    int tid = threadIdx.x;
    for (int i = tid; i < 1024; i += 256) {
        float top = W_msg[i];
        float bot = W_msg[1024 + i];
        sA[i] = top - bot;
        sB[i] = bot;
    }
    if (tid < 32) {
        sbm[tid] = b_msg[tid];
        const float invN = 1.f / (float)NN;
        float mu  = g_stats[tid] * invN;
        float var = g_stats[HD + tid] * invN - mu * mu;
        float s   = gamma[tid] * rsqrtf(var + 1e-5f);
        ss1[tid] = s;
        st1[tid] = beta[tid] - mu * s;
    }
    __syncthreads();

    int n = blockIdx.x * 256 + tid;
    if (n >= NN) return;

    float e[32];
    const float4* src = (const float4*)(g_emb_pre + (size_t)n * HD);
    #pragma unroll
    for (int v = 0; v < 8; v++) {
        float4 f = src[v];
        e[4 * v + 0] = f.x; e[4 * v + 1] = f.y; e[4 * v + 2] = f.z; e[4 * v + 3] = f.w;
    }
    #pragma unroll
    for (int j = 0; j < 32; j++) e[j] = fmaf(e[j], ss1[j], st1[j]);

    float4* de = (float4*)(g_emb + (size_t)n * HD);
    #pragma unroll
    for (int v = 0; v < 8; v++)
        de[v] = make_float4(e[4 * v], e[4 * v + 1], e[4 * v + 2], e[4 * v + 3]);

    float p[32], q[32];
    #pragma unroll
    for (int j = 0; j < 32; j++) { p[j] = sbm[j]; q[j] = 0.f; }
    #pragma unroll 4
    for (int k = 0; k < 32; k++) {
        float ek = e[k];
        #pragma unroll
        for (int j = 0; j < 32; j++) {
            p[j] = fmaf(ek, sA[k * 32 + j], p[j]);
            q[j] = fmaf(ek, sB[k * 32 + j], q[j]);
        }
    }

    float4* dq = (float4*)(g_q  + (size_t)n * HD);
    float4* dp = (float4*)(g_pb + (size_t)n * HD);
    #pragma unroll
    for (int v = 0; v < 8; v++) {
        dq[v] = make_float4(q[4 * v], q[4 * v + 1], q[4 * v + 2], q[4 * v + 3]);
        dp[v] = make_float4(p[4 * v], p[4 * v + 1], p[4 * v + 2], p[4 * v + 3]);
    }
}

// ---- K7: CSR segment max. warp = 1 dst node, lane = feature.
//      No atomics: register fmax over incoming edges. ----
__global__ void __launch_bounds__(256) k_maxagg() {
    int w = (blockIdx.x * 256 + threadIdx.x) >> 5;   // dst node
    int h = threadIdx.x & 31;                         // feature
    if (w >= NN) return;
    int beg = __ldg(&g_off[w]);
    int end = __ldg(&g_off[w + 1]);
    float m = -3.402823466e+38f;
    int e = beg;
    for (; e + 3 < end; e += 4) {
        int s0 = __ldg(&g_srcs[e + 0]);
        int s1 = __ldg(&g_srcs[e + 1]);
        int s2 = __ldg(&g_srcs[e + 2]);
        int s3 = __ldg(&g_srcs[e + 3]);
        float v0 = __ldg(&g_q[(size_t)s0 * HD + h]);
        float v1 = __ldg(&g_q[(size_t)s1 * HD + h]);
        float v2 = __ldg(&g_q[(size_t)s2 * HD + h]);
        float v3 = __ldg(&g_q[(size_t)s3 * HD + h]);
        m = fmaxf(m, fmaxf(fmaxf(v0, v1), fmaxf(v2, v3)));
    }
    for (; e < end; e++) {
        int s = __ldg(&g_srcs[e]);
        m = fmaxf(m, __ldg(&g_q[(size_t)s * HD + h]));
    }
    float a = (end > beg) ? (__ldg(&g_pb[(size_t)w * HD + h]) + m) : 0.f;
    g_agg[(size_t)w * HD + h] = a;
}

// ---- K8: column stats of g_agg -> sum2/sq2 ----
__global__ void __launch_bounds__(256) k_stats_agg() {
    float acc_s = 0.f, acc_q = 0.f;
    long stride = (long)gridDim.x * 256;
    for (long i = (long)blockIdx.x * 256 + threadIdx.x; i < (long)NN * HD; i += stride) {
        float v = g_agg[i];
        acc_s += v;
        acc_q += v * v;
    }
    __shared__ float ss[256], sq[256];
    int t = threadIdx.x;
    ss[t] = acc_s; sq[t] = acc_q;
    __syncthreads();
    if (t < 32) {
        #pragma unroll
        for (int w = 1; w < 8; w++) { acc_s += ss[t + 32 * w]; acc_q += sq[t + 32 * w]; }
        atomicAdd(&g_stats[2 * HD + t], acc_s);
        atomicAdd(&g_stats[3 * HD + t], acc_q);
    }
}

// ---- K9: residual + BN2 (inline params) + output MLP ----
__global__ void __launch_bounds__(256) k_out(
    const float* __restrict__ gamma, const float* __restrict__ beta,
    const float* __restrict__ W_out1, const float* __restrict__ b_out1,
    const float* __restrict__ W_out2, const float* __restrict__ b_out2,
    float* __restrict__ out)
{
    __shared__ float sW1[512], sb1[16], sW2[16], ss2[32], st2[32];
    __shared__ float sb2;
    int tid = threadIdx.x;
    for (int i = tid; i < 512; i += 256) sW1[i] = W_out1[i];
    if (tid < 16) { sb1[tid] = b_out1[tid]; sW2[tid] = W_out2[tid]; }
    if (tid < 32) {
        const float invN = 1.f / (float)NN;
        float mu  = g_stats[2 * HD + tid] * invN;
        float var = g_stats[3 * HD + tid] * invN - mu * mu;
        float s   = gamma[tid] * rsqrtf(var + 1e-5f);
        ss2[tid] = s;
        st2[tid] = beta[tid] - mu * s;
    }
    if (tid == 0) sb2 = b_out2[0];
    __syncthreads();

    int n = blockIdx.x * 256 + tid;
    if (n >= NN) return;

    float x[32];
    const float4* fe = (const float4*)(g_emb + (size_t)n * HD);
    const float4* fa = (const float4*)(g_agg + (size_t)n * HD);
    #pragma unroll
    for (int v = 0; v < 8; v++) {
        float4 em = fe[v], ag = fa[v];
        float a4[4] = {ag.x, ag.y, ag.z, ag.w};
        float e4[4] = {em.x, em.y, em.z, em.w};
        #pragma unroll
        for (int u = 0; u < 4; u++) {
            int j = v * 4 + u;
            x[j] = e4[u] + fmaf(a4[u], ss2[j], st2[j]);
        }
    }

    float h[16];
    #pragma unroll
    for (int j = 0; j < 16; j++) {
        float a = sb1[j];
        #pragma unroll
        for (int k = 0; k < 32; k++) a = fmaf(x[k], sW1[k * 16 + j], a);
        h[j] = eluf(a);
    }
    float o = sb2;
    #pragma unroll
    for (int k = 0; k < 16; k++) o = fmaf(h[k], sW2[k], o);
    out[n] = o;
}

extern "C" void kernel_launch(void* const* d_in, const int* in_sizes, int n_in,
                              void* d_out, int out_size) {
    const float* x_cont  = (const float*)d_in[0];
    const int*   x_cat   = (const int*)  d_in[1];
    const int*   ei      = (const int*)  d_in[2];
    /* d_in[3] = batch (all zeros, unused) */
    const float* W_cont  = (const float*)d_in[4];
    const float* b_cont  = (const float*)d_in[5];
    const float* T_chrg  = (const float*)d_in[6];
    const float* T_pdg   = (const float*)d_in[7];
    const float* T_pv    = (const float*)d_in[8];
    const float* W_cat   = (const float*)d_in[9];
    const float* b_cat   = (const float*)d_in[10];
    const float* W_enc   = (const float*)d_in[11];
    const float* b_enc   = (const float*)d_in[12];
    const float* g_all   = (const float*)d_in[13];
    const float* be_all  = (const float*)d_in[14];
    const float* W_msg   = (const float*)d_in[15];
    const float* b_msg   = (const float*)d_in[16];
    const float* g_conv  = (const float*)d_in[17];
    const float* be_conv = (const float*)d_in[18];
    const float* W_out1  = (const float*)d_in[19];
    const float* b_out1  = (const float*)d_in[20];
    const float* W_out2  = (const float*)d_in[21];
    const float* b_out2  = (const float*)d_in[22];
    float* out = (float*)d_out;

    const int nb = (NN + 255) / 256;            // 391
    const int ebE = (NE + 255) / 256;           // 6250
    const int mb = (NN * HD + 255) / 256;       // 12500

    k_init<<<(NN + 1023) / 1024, 1024>>>();
    k_embed<<<nb, 256>>>(x_cont, x_cat, W_cont, b_cont, T_chrg, T_pdg, T_pv,
                         W_cat, b_cat, W_enc, b_enc);
    k_hist<<<ebE, 256>>>(ei);
    k_scan<<<1, 1024>>>();
    k_scatter<<<ebE, 256>>>(ei);
    k_stats_pre<<<132, 256>>>();
    k_pq<<<nb, 256>>>(W_msg, b_msg, g_all, be_all);
    k_maxagg<<<mb, 256>>>();
    k_stats_agg<<<132, 256>>>();
    k_out<<<nb, 256>>>(g_conv, be_conv, W_out1, b_out1, W_out2, b_out2, out);
}

// round 6
// speedup vs baseline: 2.8000x; 2.8000x over previous
#include <cuda_runtime.h>
#include <math.h>

#define NN 100000
#define NE 1600000
#define HD 32
#define NB 391   // (NN+255)/256

// ---- scratch (__device__ globals: no allocations allowed) ----
__device__ float g_emb_pre[NN * HD];   // pre-batchnorm node embedding
__device__ float g_emb[NN * HD];       // post-batchnorm node embedding
__device__ float g_q[NN * HD];         // emb @ W_bot           (per-src term)
__device__ float g_pb[NN * HD];        // emb @ (W_top-W_bot)+b (per-dst term)
__device__ float g_agg[NN * HD];       // final aggregated message (0 if empty)
__device__ float g_stats[4 * HD];      // sum1, sq1, sum2, sq2
__device__ int   g_deg[NN];            // in-degree histogram
__device__ int   g_off[NN + 1];        // CSR offsets
__device__ int   g_cur[NN];            // scatter cursors
__device__ int   g_srcs[NE];           // src node ids grouped by dst
__device__ int   g_part[NB];           // per-block degree sums
__device__ int   g_pscan[NB];          // exclusive scan of block sums

__device__ __forceinline__ float eluf(float x) { return x > 0.f ? x : expm1f(x); }

// ---- K0: zero stats + degree histogram ----
__global__ void __launch_bounds__(1024) k_init() {
    int i = blockIdx.x * 1024 + threadIdx.x;
    if (i < 4 * HD) g_stats[i] = 0.f;
    if (i < NN) g_deg[i] = 0;
}

// ---- K1: node feature encoder -> g_emb_pre ----
__global__ void __launch_bounds__(256) k_embed(
    const float* __restrict__ x_cont, const int* __restrict__ x_cat,
    const float* __restrict__ W_cont, const float* __restrict__ b_cont,
    const float* __restrict__ T_chrg, const float* __restrict__ T_pdg,
    const float* __restrict__ T_pv,
    const float* __restrict__ W_cat,  const float* __restrict__ b_cat,
    const float* __restrict__ W_enc,  const float* __restrict__ b_enc)
{
    __shared__ float sWc[96], sbc[16], sTc[24], sTp[56], sTv[64];
    __shared__ float sWk[384], sbk[16], sWe[1024], sbe[32];
    int tid = threadIdx.x;
    for (int i = tid; i < 96;   i += 256) sWc[i] = W_cont[i];
    for (int i = tid; i < 16;   i += 256) sbc[i] = b_cont[i];
    for (int i = tid; i < 24;   i += 256) sTc[i] = T_chrg[i];
    for (int i = tid; i < 56;   i += 256) sTp[i] = T_pdg[i];
    for (int i = tid; i < 64;   i += 256) sTv[i] = T_pv[i];
    for (int i = tid; i < 384;  i += 256) sWk[i] = W_cat[i];
    for (int i = tid; i < 16;   i += 256) sbk[i] = b_cat[i];
    for (int i = tid; i < 1024; i += 256) sWe[i] = W_enc[i];
    for (int i = tid; i < 32;   i += 256) sbe[i] = b_enc[i];
    __syncthreads();

    int n = blockIdx.x * 256 + tid;
    if (n >= NN) return;

    float c[6];
    #pragma unroll
    for (int k = 0; k < 6; k++) c[k] = x_cont[n * 6 + k];
    float h1[16];
    #pragma unroll
    for (int j = 0; j < 16; j++) {
        float a = sbc[j];
        #pragma unroll
        for (int k = 0; k < 6; k++) a += c[k] * sWc[k * 16 + j];
        h1[j] = eluf(a);
    }

    int pdg_s = x_cat[n * 3 + 0];
    int chrg  = x_cat[n * 3 + 1];
    int pv    = x_cat[n * 3 + 2];
    int ap = pdg_s < 0 ? -pdg_s : pdg_s;
    int pi;
    switch (ap) {
        case 1:   pi = 0; break;
        case 2:   pi = 1; break;
        case 11:  pi = 2; break;
        case 13:  pi = 3; break;
        case 22:  pi = 4; break;
        case 130: pi = 5; break;
        default:  pi = 6; break;  // 211
    }
    float cat24[24];
    #pragma unroll
    for (int j = 0; j < 8; j++) {
        cat24[j]      = sTc[(chrg + 1) * 8 + j];
        cat24[8 + j]  = sTp[pi * 8 + j];
        cat24[16 + j] = sTv[pv * 8 + j];
    }
    float h2[16];
    #pragma unroll
    for (int j = 0; j < 16; j++) {
        float a = sbk[j];
        #pragma unroll
        for (int k = 0; k < 24; k++) a += cat24[k] * sWk[k * 16 + j];
        h2[j] = eluf(a);
    }

    float4* dst = (float4*)(g_emb_pre + (size_t)n * HD);
    #pragma unroll
    for (int jv = 0; jv < 8; jv++) {
        float o[4];
        #pragma unroll
        for (int u = 0; u < 4; u++) {
            int j = jv * 4 + u;
            float a = sbe[j];
            #pragma unroll
            for (int k = 0; k < 16; k++) a += h2[k] * sWe[k * 32 + j];
            #pragma unroll
            for (int k = 0; k < 16; k++) a += h1[k] * sWe[(16 + k) * 32 + j];
            o[u] = eluf(a);
        }
        dst[jv] = make_float4(o[0], o[1], o[2], o[3]);
    }
}

// ---- K2: degree histogram over destinations ----
__global__ void __launch_bounds__(256) k_hist(const int* __restrict__ ei) {
    int e = blockIdx.x * 256 + threadIdx.x;
    if (e < NE) atomicAdd(&g_deg[__ldg(&ei[NE + e])], 1);
}

// ---- K3a: per-block degree sums ----
__global__ void __launch_bounds__(256) k_part() {
    int id = blockIdx.x * 256 + threadIdx.x;
    int d = (id < NN) ? g_deg[id] : 0;
    #pragma unroll
    for (int o = 16; o; o >>= 1) d += __shfl_down_sync(0xffffffffu, d, o);
    __shared__ int ws[8];
    if ((threadIdx.x & 31) == 0) ws[threadIdx.x >> 5] = d;
    __syncthreads();
    if (threadIdx.x < 8) {
        int v = ws[threadIdx.x];
        #pragma unroll
        for (int o = 4; o; o >>= 1) v += __shfl_down_sync(0xffu, v, o);
        if (threadIdx.x == 0) g_part[blockIdx.x] = v;
    }
}

// ---- K3b: scan the 391 block sums (single small block; tiny) ----
__global__ void __launch_bounds__(512) k_scanpart() {
    __shared__ int sh[512];
    int t = threadIdx.x;
    sh[t] = (t < NB) ? g_part[t] : 0;
    __syncthreads();
    #pragma unroll
    for (int off = 1; off < 512; off <<= 1) {
        int v = (t >= off) ? sh[t - off] : 0;
        __syncthreads();
        sh[t] += v;
        __syncthreads();
    }
    if (t < NB) g_pscan[t] = (t == 0) ? 0 : sh[t - 1];
}

// ---- K3c: block-local scan + carry -> g_off, g_cur ----
__global__ void __launch_bounds__(256) k_off() {
    __shared__ int sh[256];
    int t = threadIdx.x;
    int id = blockIdx.x * 256 + t;
    int d = (id < NN) ? g_deg[id] : 0;
    sh[t] = d;
    __syncthreads();
    #pragma unroll
    for (int off = 1; off < 256; off <<= 1) {
        int v = (t >= off) ? sh[t - off] : 0;
        __syncthreads();
        sh[t] += v;
        __syncthreads();
    }
    int incl = sh[t];
    int carry = g_pscan[blockIdx.x];
    if (id < NN) {
        int o = carry + incl - d;
        g_off[id] = o;
        g_cur[id] = o;
        if (id == NN - 1) g_off[NN] = carry + incl;
    }
}

// ---- K4: scatter src ids grouped by dst ----
__global__ void __launch_bounds__(256) k_scatter(const int* __restrict__ ei) {
    int e = blockIdx.x * 256 + threadIdx.x;
    if (e >= NE) return;
    int src = __ldg(&ei[e]);
    int dst = __ldg(&ei[NE + e]);
    int p = atomicAdd(&g_cur[dst], 1);
    g_srcs[p] = src;
}

// ---- K5a: column stats of g_emb_pre -> sum1/sq1 ----
__global__ void __launch_bounds__(256) k_stats_pre() {
    float acc_s = 0.f, acc_q = 0.f;
    long stride = (long)gridDim.x * 256;
    for (long i = (long)blockIdx.x * 256 + threadIdx.x; i < (long)NN * HD; i += stride) {
        float v = g_emb_pre[i];
        acc_s += v;
        acc_q += v * v;
    }
    __shared__ float ss[256], sq[256];
    int t = threadIdx.x;
    ss[t] = acc_s; sq[t] = acc_q;
    __syncthreads();
    if (t < 32) {
        #pragma unroll
        for (int w = 1; w < 8; w++) { acc_s += ss[t + 32 * w]; acc_q += sq[t + 32 * w]; }
        atomicAdd(&g_stats[t], acc_s);
        atomicAdd(&g_stats[HD + t], acc_q);
    }
}

// ---- K6: apply BN1 (params inline), q = emb@W_bot, pb = emb@(W_top-W_bot)+b ----
__global__ void __launch_bounds__(256) k_pq(const float* __restrict__ W_msg,
                                            const float* __restrict__ b_msg,
                                            const float* __restrict__ gamma,
                                            const float* __restrict__ beta) {
    __shared__ float sA[1024], sB[1024], sbm[32], ss1[32], st1[32];
    int tid = threadIdx.x;
    for (int i = tid; i < 1024; i += 256) {
        float top = W_msg[i];
        float bot = W_msg[1024 + i];
        sA[i] = top - bot;
        sB[i] = bot;
    }
    if (tid < 32) {
        sbm[tid] = b_msg[tid];
        const float invN = 1.f / (float)NN;
        float mu  = g_stats[tid] * invN;
        float var = g_stats[HD + tid] * invN - mu * mu;
        float s   = gamma[tid] * rsqrtf(var + 1e-5f);
        ss1[tid] = s;
        st1[tid] = beta[tid] - mu * s;
    }
    __syncthreads();

    int n = blockIdx.x * 256 + tid;
    if (n >= NN) return;

    float e[32];
    const float4* src = (const float4*)(g_emb_pre + (size_t)n * HD);
    #pragma unroll
    for (int v = 0; v < 8; v++) {
        float4 f = src[v];
        e[4 * v + 0] = f.x; e[4 * v + 1] = f.y; e[4 * v + 2] = f.z; e[4 * v + 3] = f.w;
    }
    #pragma unroll
    for (int j = 0; j < 32; j++) e[j] = fmaf(e[j], ss1[j], st1[j]);

    float4* de = (float4*)(g_emb + (size_t)n * HD);
    #pragma unroll
    for (int v = 0; v < 8; v++)
        de[v] = make_float4(e[4 * v], e[4 * v + 1], e[4 * v + 2], e[4 * v + 3]);

    float p[32], q[32];
    #pragma unroll
    for (int j = 0; j < 32; j++) { p[j] = sbm[j]; q[j] = 0.f; }
    #pragma unroll 4
    for (int k = 0; k < 32; k++) {
        float ek = e[k];
        #pragma unroll
        for (int j = 0; j < 32; j++) {
            p[j] = fmaf(ek, sA[k * 32 + j], p[j]);
            q[j] = fmaf(ek, sB[k * 32 + j], q[j]);
        }
    }

    float4* dq = (float4*)(g_q  + (size_t)n * HD);
    float4* dp = (float4*)(g_pb + (size_t)n * HD);
    #pragma unroll
    for (int v = 0; v < 8; v++) {
        dq[v] = make_float4(q[4 * v], q[4 * v + 1], q[4 * v + 2], q[4 * v + 3]);
        dp[v] = make_float4(p[4 * v], p[4 * v + 1], p[4 * v + 2], p[4 * v + 3]);
    }
}

// ---- K7: CSR segment max. warp = 1 dst node, lane = feature. No atomics. ----
__global__ void __launch_bounds__(256) k_maxagg() {
    int w = (blockIdx.x * 256 + threadIdx.x) >> 5;   // dst node
    int h = threadIdx.x & 31;                         // feature
    if (w >= NN) return;
    int beg = __ldg(&g_off[w]);
    int end = __ldg(&g_off[w + 1]);
    float m = -3.402823466e+38f;
    int e = beg;
    for (; e + 3 < end; e += 4) {
        int s0 = __ldg(&g_srcs[e + 0]);
        int s1 = __ldg(&g_srcs[e + 1]);
        int s2 = __ldg(&g_srcs[e + 2]);
        int s3 = __ldg(&g_srcs[e + 3]);
        float v0 = __ldg(&g_q[(size_t)s0 * HD + h]);
        float v1 = __ldg(&g_q[(size_t)s1 * HD + h]);
        float v2 = __ldg(&g_q[(size_t)s2 * HD + h]);
        float v3 = __ldg(&g_q[(size_t)s3 * HD + h]);
        m = fmaxf(m, fmaxf(fmaxf(v0, v1), fmaxf(v2, v3)));
    }
    for (; e < end; e++) {
        int s = __ldg(&g_srcs[e]);
        m = fmaxf(m, __ldg(&g_q[(size_t)s * HD + h]));
    }
    float a = (end > beg) ? (__ldg(&g_pb[(size_t)w * HD + h]) + m) : 0.f;
    g_agg[(size_t)w * HD + h] = a;
}

// ---- K8: column stats of g_agg -> sum2/sq2 ----
__global__ void __launch_bounds__(256) k_stats_agg() {
    float acc_s = 0.f, acc_q = 0.f;
    long stride = (long)gridDim.x * 256;
    for (long i = (long)blockIdx.x * 256 + threadIdx.x; i < (long)NN * HD; i += stride) {
        float v = g_agg[i];
        acc_s += v;
        acc_q += v * v;
    }
    __shared__ float ss[256], sq[256];
    int t = threadIdx.x;
    ss[t] = acc_s; sq[t] = acc_q;
    __syncthreads();
    if (t < 32) {
        #pragma unroll
        for (int w = 1; w < 8; w++) { acc_s += ss[t + 32 * w]; acc_q += sq[t + 32 * w]; }
        atomicAdd(&g_stats[2 * HD + t], acc_s);
        atomicAdd(&g_stats[3 * HD + t], acc_q);
    }
}

// ---- K9: residual + BN2 (inline params) + output MLP ----
__global__ void __launch_bounds__(256) k_out(
    const float* __restrict__ gamma, const float* __restrict__ beta,
    const float* __restrict__ W_out1, const float* __restrict__ b_out1,
    const float* __restrict__ W_out2, const float* __restrict__ b_out2,
    float* __restrict__ out)
{
    __shared__ float sW1[512], sb1[16], sW2[16], ss2[32], st2[32];
    __shared__ float sb2;
    int tid = threadIdx.x;
    for (int i = tid; i < 512; i += 256) sW1[i] = W_out1[i];
    if (tid < 16) { sb1[tid] = b_out1[tid]; sW2[tid] = W_out2[tid]; }
    if (tid < 32) {
        const float invN = 1.f / (float)NN;
        float mu  = g_stats[2 * HD + tid] * invN;
        float var = g_stats[3 * HD + tid] * invN - mu * mu;
        float s   = gamma[tid] * rsqrtf(var + 1e-5f);
        ss2[tid] = s;
        st2[tid] = beta[tid] - mu * s;
    }
    if (tid == 0) sb2 = b_out2[0];
    __syncthreads();

    int n = blockIdx.x * 256 + tid;
    if (n >= NN) return;

    float x[32];
    const float4* fe = (const float4*)(g_emb + (size_t)n * HD);
    const float4* fa = (const float4*)(g_agg + (size_t)n * HD);
    #pragma unroll
    for (int v = 0; v < 8; v++) {
        float4 em = fe[v], ag = fa[v];
        float a4[4] = {ag.x, ag.y, ag.z, ag.w};
        float e4[4] = {em.x, em.y, em.z, em.w};
        #pragma unroll
        for (int u = 0; u < 4; u++) {
            int j = v * 4 + u;
            x[j] = e4[u] + fmaf(a4[u], ss2[j], st2[j]);
        }
    }

    float h[16];
    #pragma unroll
    for (int j = 0; j < 16; j++) {
        float a = sb1[j];
        #pragma unroll
        for (int k = 0; k < 32; k++) a = fmaf(x[k], sW1[k * 16 + j], a);
        h[j] = eluf(a);
    }
    float o = sb2;
    #pragma unroll
    for (int k = 0; k < 16; k++) o = fmaf(h[k], sW2[k], o);
    out[n] = o;
}

extern "C" void kernel_launch(void* const* d_in, const int* in_sizes, int n_in,
                              void* d_out, int out_size) {
    const float* x_cont  = (const float*)d_in[0];
    const int*   x_cat   = (const int*)  d_in[1];
    const int*   ei      = (const int*)  d_in[2];
    /* d_in[3] = batch (all zeros, unused) */
    const float* W_cont  = (const float*)d_in[4];
    const float* b_cont  = (const float*)d_in[5];
    const float* T_chrg  = (const float*)d_in[6];
    const float* T_pdg   = (const float*)d_in[7];
    const float* T_pv    = (const float*)d_in[8];
    const float* W_cat   = (const float*)d_in[9];
    const float* b_cat   = (const float*)d_in[10];
    const float* W_enc   = (const float*)d_in[11];
    const float* b_enc   = (const float*)d_in[12];
    const float* g_all   = (const float*)d_in[13];
    const float* be_all  = (const float*)d_in[14];
    const float* W_msg   = (const float*)d_in[15];
    const float* b_msg   = (const float*)d_in[16];
    const float* g_conv  = (const float*)d_in[17];
    const float* be_conv = (const float*)d_in[18];
    const float* W_out1  = (const float*)d_in[19];
    const float* b_out1  = (const float*)d_in[20];
    const float* W_out2  = (const float*)d_in[21];
    const float* b_out2  = (const float*)d_in[22];
    float* out = (float*)d_out;

    const int nb  = NB;                       // 391
    const int ebE = (NE + 255) / 256;         // 6250
    const int mb  = (NN * HD + 255) / 256;    // 12500

    k_init<<<(NN + 1023) / 1024, 1024>>>();
    k_embed<<<nb, 256>>>(x_cont, x_cat, W_cont, b_cont, T_chrg, T_pdg, T_pv,
                         W_cat, b_cat, W_enc, b_enc);
    k_hist<<<ebE, 256>>>(ei);
    k_part<<<nb, 256>>>();
    k_scanpart<<<1, 512>>>();
    k_off<<<nb, 256>>>();
    k_scatter<<<ebE, 256>>>(ei);
    k_stats_pre<<<132, 256>>>();
    k_pq<<<nb, 256>>>(W_msg, b_msg, g_all, be_all);
    k_maxagg<<<mb, 256>>>();
    k_stats_agg<<<132, 256>>>();
    k_out<<<nb, 256>>>(g_conv, be_conv, W_out1, b_out1, W_out2, b_out2, out);
}